// round 16
// baseline (speedup 1.0000x reference)
#include <cuda_runtime.h>

// ---------------------------------------------------------------------------
// Quantized LSTM — TWO steps per grid barrier (batched speculative verify).
// Pair (t, t+1): both steps computed with predicted exponents (k1,ka,k3,kh);
// h(t) written speculatively (needed by pre(t+1)). One barrier reduces 16
// cells (8 per step) + 1 counter add. Verify order: step-t gate cells always
// exact; if step t fully hits (incl. kh), step t+1 cells are exact.
// Tiered globally-uniform fixups (rare) replay the contaminated suffix from
// persisted pre0/pre1/c_m1/c_m0/hp0 via R6-proven synchronous rounds.
// ---------------------------------------------------------------------------

#define GB       128
#define BPB      8
#define NT       640
#define T_STEPS  1024
#define PAIRS    (T_STEPS / 2)
#define NI       10
#define NH       20
#define NG       80
#define CSTRIDE  64              // 256B between cells
#define NCELL    32              // 0-7 t, 8-15 u, 16-27 fixup slots

__device__ __align__(128) unsigned g_ctr0[32];
__device__ unsigned g_cells[PAIRS * NCELL * CSTRIDE];

__global__ void qlstm_init() {
    int i = blockIdx.x * blockDim.x + threadIdx.x;   // 16384 = PAIRS*NCELL
    if (i == 0) g_ctr0[0] = 0u;
    if (i < PAIRS * NCELL) g_cells[i * CSTRIDE] = 0u;
}

__device__ __forceinline__ unsigned mapf(float f) {
    unsigned u = __float_as_uint(f);
    return (u & 0x80000000u) ? ~u : (u | 0x80000000u);
}
__device__ __forceinline__ float unmapf(unsigned u) {
    return __uint_as_float((u & 0x80000000u) ? (u & 0x7FFFFFFFu) : ~u);
}
__device__ __forceinline__ int po2k(float m) {
    m = fmaxf(m, 1e-8f);
    int e; float f = frexpf(m, &e);
    return (f == 0.5f) ? (e - 1) : e;
}
__device__ __forceinline__ float sc(int k)    { return __uint_as_float((unsigned)(k + 120) << 23); }
__device__ __forceinline__ float scinv(int k) { return __uint_as_float((unsigned)(134 - k) << 23); }
__device__ __forceinline__ float fq1(float x, float s, float inv) {
    float q = rintf(x * inv);
    q = fminf(fmaxf(q, -128.0f), 127.0f);
    return q * s;
}
__device__ __forceinline__ float sigm(float x) { return 1.0f / (1.0f + expf(-x)); }
__device__ __forceinline__ unsigned warp_max_u(unsigned v) {
#pragma unroll
    for (int o = 16; o; o >>= 1) v = max(v, __shfl_xor_sync(0xffffffffu, v, o));
    return v;
}
__device__ __forceinline__ void red_max_rlx(unsigned* p, unsigned v) {
    asm volatile("red.relaxed.gpu.max.u32 [%0],%1;" :: "l"(p), "r"(v) : "memory");
}
__device__ __forceinline__ unsigned atom_add_acqrel(unsigned* p, unsigned v) {
    unsigned old;
    asm volatile("atom.acq_rel.gpu.add.u32 %0,[%1],%2;" : "=r"(old) : "l"(p), "r"(v) : "memory");
    return old;
}
__device__ __forceinline__ unsigned ld_acq(const unsigned* p) {
    unsigned v; asm volatile("ld.acquire.gpu.u32 %0,[%1];" : "=r"(v) : "l"(p) : "memory"); return v;
}
__device__ __forceinline__ unsigned ld_rlx(const unsigned* p) {
    unsigned v; asm volatile("ld.relaxed.gpu.u32 %0,[%1];" : "=r"(v) : "l"(p) : "memory"); return v;
}

// warp0-collective grid round: CG-style single-lane poll.
__device__ __forceinline__ unsigned grid_bar(unsigned* cell0, unsigned myv, int nc,
                                             unsigned tgt, int lane) {
    if (lane < nc) red_max_rlx(cell0 + lane * CSTRIDE, myv);
    __syncwarp();
    if (lane == 0) {
        unsigned o = atom_add_acqrel(&g_ctr0[0], 1u);
        if (o != tgt - 1u) { while (ld_acq(&g_ctr0[0]) < tgt) { } }
    }
    __syncwarp();
    return (lane < nc) ? ld_rlx(cell0 + lane * CSTRIDE) : 0u;
}

__global__ void __launch_bounds__(NT, 1) qlstm_main(
    const float* __restrict__ x,
    const float* __restrict__ Wih,
    const float* __restrict__ Whh,
    float* __restrict__ out)
{
    __shared__ __align__(16) float sh_h[2][BPB * NH];   // h(u) in slot u&1
    __shared__ __align__(16) float sh_x[4][BPB * NI];   // x ring
    __shared__ float               sh_act[NG * BPB];
    __shared__ unsigned            sh_red[24];  // 0-9 step t, 12-21 step u, 10/11 fix, 22 wscale
    __shared__ int                 sh_k[16];    // 0:k1t 1-4:kat 5:k3t 6:kht 7:code
                                                // 8:k1u 9-12:kau 13:k3u 14:khu
    __shared__ int                 sh_kp[8];    // preds: k1, ka0-3, k3, kh

    const int tid  = threadIdx.x;
    const int bid  = blockIdx.x;
    const int g    = tid / BPB;
    const int b    = tid % BPB;
    const int gr   = tid / 160;          // warp-uniform gate group
    const int lane = tid & 31;
    const int wid  = tid >> 5;

    if (tid < 24) sh_red[tid] = 0u;
    if (tid < 8)  sh_kp[tid] = 99;       // garbage -> full replay at pair 0
    if (tid < 16) sh_k[tid] = 0;
    if (tid < BPB * NH) { sh_h[0][tid] = 0.0f; sh_h[1][tid] = 0.0f; }
    __syncthreads();

    // ---- weight scale (block-local, once) ----
    {
        float wm = 0.0f;
        for (int k = tid; k < NG * NI; k += NT) wm = fmaxf(wm, fabsf(Wih[k]));
        for (int k = tid; k < NG * NH; k += NT) wm = fmaxf(wm, fabsf(Whh[k]));
        unsigned u = warp_max_u(__float_as_uint(wm));
        if (lane == 0) atomicMax(&sh_red[22], u);
        __syncthreads();
    }
    int kw = po2k(__uint_as_float(sh_red[22]));
    float ws = sc(kw), wsi = scinv(kw);
    __syncthreads();
    if (tid == 0) sh_red[22] = 0u;
    __syncthreads();

    float wi[NI], wh[NH];
#pragma unroll
    for (int i2 = 0; i2 < NI; i2++) wi[i2] = fq1(Wih[g * NI + i2], ws, wsi);
#pragma unroll
    for (int j2 = 0; j2 < NH; j2++) wh[j2] = fq1(Whh[g * NH + j2], ws, wsi);

    // persistent state
    float    c = 0.0f, c_m1 = 0.0f, c_m0 = 0.0f;
    float    pre0 = 0.0f, pre1 = 0.0f, hp0 = 0.0f;
    float    tc1 = 0.0f, oq1 = 0.0f, hp1 = 0.0f;
    unsigned nbar = 0;

    const int sq  = tid - 560;           // warps 17-19 stage x
    const int sxb = (sq >= 0) ? sq / NI : 0;
    const int sxi = (sq >= 0) ? sq % NI : 0;
    float xr2 = 0.0f, xr3 = 0.0f;
    if (sq >= 0) {
        sh_x[0][sq] = x[((size_t)(bid * BPB + sxb) * T_STEPS + 0) * NI + sxi];
        sh_x[1][sq] = x[((size_t)(bid * BPB + sxb) * T_STEPS + 1) * NI + sxi];
        xr2         = x[((size_t)(bid * BPB + sxb) * T_STEPS + 2) * NI + sxi];
        xr3         = x[((size_t)(bid * BPB + sxb) * T_STEPS + 3) * NI + sxi];
    }
    __syncthreads();

    for (int t = 0; t < T_STEPS; t += 2) {
        const int pair = t >> 1;
        unsigned* cb_ = &g_cells[(size_t)pair * NCELL * CSTRIDE];
        const int k1p = sh_kp[0], kap = sh_kp[1 + gr], k3p = sh_kp[5], khp = sh_kp[6];

        // =============== phase B(t): pre0, extrema, spec act ===============
        {
            float p0 = 0.0f, p1 = 0.0f;
            const float2* px = reinterpret_cast<const float2*>(&sh_x[t & 3][b * NI]);
            const float2* ph = reinterpret_cast<const float2*>(&sh_h[(t + 1) & 1][b * NH]);
#pragma unroll
            for (int j = 0; j < NI / 2; j++) {
                float2 v = px[j];
                p0 = fmaf(v.x, wi[2 * j], p0); p1 = fmaf(v.y, wi[2 * j + 1], p1);
            }
#pragma unroll
            for (int j = 0; j < NH / 2; j++) {
                float2 v = ph[j];
                p0 = fmaf(v.x, wh[2 * j], p0); p1 = fmaf(v.y, wh[2 * j + 1], p1);
            }
            pre0 = p0 + p1;
        }
        {
            unsigned kp = warp_max_u(mapf(pre0));
            unsigned kn = warp_max_u(mapf(-pre0));
            if (lane == 0) { atomicMax(&sh_red[gr], kp); atomicMax(&sh_red[4 + gr], kn); }
            float gq  = fq1(pre0, sc(k1p), scinv(k1p));
            float act = (gr == 2) ? tanhf(gq) : sigm(gq);
            sh_act[tid] = fq1(act, sc(kap), scinv(kap));
        }
        __syncthreads();                                        // S1
        if (sq >= 0 && t + 2 < T_STEPS) sh_x[(t + 2) & 3][sq] = xr2;

        // =============== phase C(t): c, tc0, hp0, speculative h(t) ===============
        if (tid < 160) {
            float iq = sh_act[tid], ff = sh_act[tid + 160], gg = sh_act[tid + 320];
            float oq0 = sh_act[tid + 480];
            c_m1 = c;
            c  = ff * c + iq * gg;
            float tc0 = tanhf(c);
            hp0 = oq0 * fq1(tc0, sc(k3p), scinv(k3p));
            float hq = fq1(hp0, sc(khp), scinv(khp));           // speculative h(t)
            sh_h[t & 1][b * NH + g] = hq;
            out[((size_t)(bid * BPB + b) * T_STEPS + t) * NH + g] = hq;
            if (wid < 5) {
                unsigned a1 = warp_max_u(__float_as_uint(fabsf(tc0)));
                unsigned a2 = warp_max_u(__float_as_uint(fabsf(hp0)));
                if (lane == 0) { atomicMax(&sh_red[8], a1); atomicMax(&sh_red[9], a2); }
            }
        }
        __syncthreads();                                        // S2

        // warp0: gather step-t extrema, fire cells 0-7 (overlaps phase B(t+1))
        if (wid == 0) {
            unsigned v = (lane < 10) ? sh_red[lane] : 0u;
            __syncwarp();
            if (lane < 10) sh_red[lane] = 0u;
            unsigned n0 = __shfl_sync(0xffffffffu, v, 4);
            unsigned n1 = __shfl_sync(0xffffffffu, v, 5);
            unsigned n2 = __shfl_sync(0xffffffffu, v, 6);
            unsigned n3 = __shfl_sync(0xffffffffu, v, 7);
            unsigned t8 = __shfl_sync(0xffffffffu, v, 8);
            unsigned t9 = __shfl_sync(0xffffffffu, v, 9);
            unsigned myv = v;
            if (lane == 4) myv = n2;
            if (lane == 5) myv = max(max(n0, n1), max(n2, n3));
            if (lane == 6) myv = t8;
            if (lane == 7) myv = t9;
            if (lane < 8) red_max_rlx(cb_ + lane * CSTRIDE, myv);
        }

        // =============== phase B(t+1): pre1 (reads h(t) spec), extrema, spec act ===============
        {
            float p0 = 0.0f, p1 = 0.0f;
            const float2* px = reinterpret_cast<const float2*>(&sh_x[(t + 1) & 3][b * NI]);
            const float2* ph = reinterpret_cast<const float2*>(&sh_h[t & 1][b * NH]);
#pragma unroll
            for (int j = 0; j < NI / 2; j++) {
                float2 v = px[j];
                p0 = fmaf(v.x, wi[2 * j], p0); p1 = fmaf(v.y, wi[2 * j + 1], p1);
            }
#pragma unroll
            for (int j = 0; j < NH / 2; j++) {
                float2 v = ph[j];
                p0 = fmaf(v.x, wh[2 * j], p0); p1 = fmaf(v.y, wh[2 * j + 1], p1);
            }
            pre1 = p0 + p1;
        }
        {
            unsigned kp = warp_max_u(mapf(pre1));
            unsigned kn = warp_max_u(mapf(-pre1));
            if (lane == 0) { atomicMax(&sh_red[12 + gr], kp); atomicMax(&sh_red[16 + gr], kn); }
            float gq  = fq1(pre1, sc(k1p), scinv(k1p));
            float act = (gr == 2) ? tanhf(gq) : sigm(gq);
            sh_act[tid] = fq1(act, sc(kap), scinv(kap));
        }
        __syncthreads();                                        // S3
        if (sq >= 0 && t + 3 < T_STEPS) sh_x[(t + 3) & 3][sq] = xr3;

        // =============== phase C(t+1): c, tc1, hp1 (NO h write) ===============
        if (tid < 160) {
            float iq = sh_act[tid], ff = sh_act[tid + 160], gg = sh_act[tid + 320];
            oq1 = sh_act[tid + 480];
            c_m0 = c;
            c  = ff * c + iq * gg;
            tc1 = tanhf(c);
            hp1 = oq1 * fq1(tc1, sc(k3p), scinv(k3p));
            if (wid < 5) {
                unsigned a1 = warp_max_u(__float_as_uint(fabsf(tc1)));
                unsigned a2 = warp_max_u(__float_as_uint(fabsf(hp1)));
                if (lane == 0) { atomicMax(&sh_red[20], a1); atomicMax(&sh_red[21], a2); }
            }
        }
        if (sq >= 0) {
            if (t + 4 < T_STEPS) xr2 = x[((size_t)(bid * BPB + sxb) * T_STEPS + (t + 4)) * NI + sxi];
            if (t + 5 < T_STEPS) xr3 = x[((size_t)(bid * BPB + sxb) * T_STEPS + (t + 5)) * NI + sxi];
        }
        __syncthreads();                                        // S4

        // =============== pair barrier: fire cells 8-15 + counter, read 16, verify ===============
        if (wid == 0) {
            unsigned v = (lane < 10) ? sh_red[12 + lane] : 0u;
            __syncwarp();
            if (lane < 10) sh_red[12 + lane] = 0u;
            unsigned n0 = __shfl_sync(0xffffffffu, v, 4);
            unsigned n1 = __shfl_sync(0xffffffffu, v, 5);
            unsigned n2 = __shfl_sync(0xffffffffu, v, 6);
            unsigned n3 = __shfl_sync(0xffffffffu, v, 7);
            unsigned t8 = __shfl_sync(0xffffffffu, v, 8);
            unsigned t9 = __shfl_sync(0xffffffffu, v, 9);
            unsigned myv = v;
            if (lane == 4) myv = n2;
            if (lane == 5) myv = max(max(n0, n1), max(n2, n3));
            if (lane == 6) myv = t8;
            if (lane == 7) myv = t9;
            if (lane < 8) red_max_rlx(cb_ + (8 + lane) * CSTRIDE, myv);
            __syncwarp();
            nbar++;
            unsigned tgt = nbar * GB;
            if (lane == 0) {
                unsigned o = atom_add_acqrel(&g_ctr0[0], 1u);
                if (o != tgt - 1u) { while (ld_acq(&g_ctr0[0]) < tgt) { } }
            }
            __syncwarp();
            unsigned cv = (lane < 16) ? ld_rlx(cb_ + lane * CSTRIDE) : 0u;

            // k1 for both steps
            unsigned at = ((lane < 4) || (lane == 5)) ? cv : 0u;
            unsigned au = ((lane >= 8 && lane < 12) || (lane == 13)) ? cv : 0u;
#pragma unroll
            for (int o = 16; o; o >>= 1) {
                at = max(at, __shfl_xor_sync(0xffffffffu, at, o));
                au = max(au, __shfl_xor_sync(0xffffffffu, au, o));
            }
            int k1t = po2k(unmapf(at));
            int k1u = po2k(unmapf(au));
            float mng_t = unmapf(__shfl_sync(0xffffffffu, cv, 4));
            float mng_u = unmapf(__shfl_sync(0xffffffffu, cv, 12));
            int grp = (lane >> 3) & 1;
            float s1 = grp ? sc(k1u) : sc(k1t);
            float v1 = grp ? scinv(k1u) : scinv(k1t);
            float mng = grp ? mng_u : mng_t;
            float myp = unmapf(cv);
            float a;
            if ((lane & 7) == 2) {
                float q1 = fq1(myp, s1, v1), q2 = fq1(-mng, s1, v1);
                a = tanhf(fmaxf(q1, -q2));
            } else {
                a = sigm(fq1(myp, s1, v1));
            }
            int ka = po2k(fabsf(a));
            int k3t = po2k(__uint_as_float(__shfl_sync(0xffffffffu, cv, 6)));
            int kht = po2k(__uint_as_float(__shfl_sync(0xffffffffu, cv, 7)));
            int k3u = po2k(__uint_as_float(__shfl_sync(0xffffffffu, cv, 14)));
            int khu = po2k(__uint_as_float(__shfl_sync(0xffffffffu, cv, 15)));
            bool ok = true;
            if (lane < 4)                 ok = (ka == sh_kp[1 + lane]);
            else if (lane >= 8 && lane < 12) ok = (ka == sh_kp[1 + lane - 8]);
            unsigned bm = __ballot_sync(0xffffffffu, ok);
            int hit1_t = (((bm & 0xFu) == 0xFu) && (k1t == sh_kp[0])) ? 1 : 0;
            int hit1_u = ((((bm >> 8) & 0xFu) == 0xFu) && (k1u == sh_kp[0])) ? 1 : 0;
            int hit3_t = (k3t == sh_kp[5]) ? 1 : 0;
            int hith_t = (kht == sh_kp[6]) ? 1 : 0;
            int hit3_u = (k3u == sh_kp[5]) ? 1 : 0;
            int code;
            if (hit1_t && hit3_t) {
                if (hith_t) code = hit1_u ? (hit3_u ? 0 : 1) : 2;
                else        code = 3;      // kh(t)-only miss: local h(t) fix + replay u
            } else          code = 4;      // full replay
            if (lane < 4)  sh_k[1 + lane] = ka;                // kat (exact)
            if (lane >= 8 && lane < 12) sh_k[1 + lane] = ka;   // kau -> sh_k[9..12]
            if (lane == 0) {
                sh_k[0] = k1t; sh_k[5] = k3t; sh_k[6] = kht;
                sh_k[8] = k1u; sh_k[13] = k3u; sh_k[14] = khu;
                sh_k[7] = code;
            }
        }
        __syncthreads();                                        // S5

        const int code = sh_k[7];

        if (code == 1) {
            // k3u miss only (tc1 exact, k3u exact): redo hp1, one round for khu
            if (tid < 160) hp1 = oq1 * fq1(tc1, sc(sh_k[13]), scinv(sh_k[13]));
            if (wid < 5) {
                unsigned aw = warp_max_u(__float_as_uint(fabsf(hp1)));
                if (lane == 0) atomicMax(&sh_red[10], aw);
            }
            __syncthreads();
            if (wid == 0) {
                unsigned v = (lane == 0) ? sh_red[10] : 0u;
                __syncwarp();
                if (lane == 0) sh_red[10] = 0u;
                nbar++;
                unsigned cv = grid_bar(cb_ + 28 * CSTRIDE, v, 1, nbar * GB, lane);
                if (lane == 0) sh_k[14] = po2k(__uint_as_float(cv));
            }
            __syncthreads();
        } else if (code == 2) {
            // step t fully ok; step u act wrong (k1/ka miss). pre1 exact; k1u/kau exact.
            {
                float gq  = fq1(pre1, sc(sh_k[8]), scinv(sh_k[8]));
                float act = (gr == 2) ? tanhf(gq) : sigm(gq);
                sh_act[tid] = fq1(act, sc(sh_k[9 + gr]), scinv(sh_k[9 + gr]));
            }
            __syncthreads();
            if (tid < 160) {
                float iq = sh_act[tid], ff = sh_act[tid + 160], gg = sh_act[tid + 320];
                oq1 = sh_act[tid + 480];
                c  = ff * c_m0 + iq * gg;
                tc1 = tanhf(c);
            }
            if (wid < 5) {
                unsigned aw = warp_max_u(__float_as_uint(fabsf(tc1)));
                if (lane == 0) atomicMax(&sh_red[10], aw);
            }
            __syncthreads();
            if (wid == 0) {
                unsigned v = (lane == 0) ? sh_red[10] : 0u;
                __syncwarp();
                if (lane == 0) sh_red[10] = 0u;
                nbar++;
                unsigned cv = grid_bar(cb_ + 26 * CSTRIDE, v, 1, nbar * GB, lane);
                if (lane == 0) sh_k[13] = po2k(__uint_as_float(cv));
            }
            __syncthreads();
            if (tid < 160) hp1 = oq1 * fq1(tc1, sc(sh_k[13]), scinv(sh_k[13]));
            if (wid < 5) {
                unsigned aw = warp_max_u(__float_as_uint(fabsf(hp1)));
                if (lane == 0) atomicMax(&sh_red[10], aw);
            }
            __syncthreads();
            if (wid == 0) {
                unsigned v = (lane == 0) ? sh_red[10] : 0u;
                __syncwarp();
                if (lane == 0) sh_red[10] = 0u;
                nbar++;
                unsigned cv = grid_bar(cb_ + 27 * CSTRIDE, v, 1, nbar * GB, lane);
                if (lane == 0) sh_k[14] = po2k(__uint_as_float(cv));
            }
            __syncthreads();
        } else if (code >= 3) {
            // ---- repair step t ----
            if (code == 3) {
                // kh(t)-only miss: hp0 exact, kht exact -> local h(t) rewrite
                if (tid < 160) {
                    float hq = fq1(hp0, sc(sh_k[6]), scinv(sh_k[6]));
                    sh_h[t & 1][b * NH + g] = hq;
                    out[((size_t)(bid * BPB + b) * T_STEPS + t) * NH + g] = hq;
                }
                __syncthreads();
            } else {
                // full replay of step t with exact k1t/kat
                {
                    float gq  = fq1(pre0, sc(sh_k[0]), scinv(sh_k[0]));
                    float act = (gr == 2) ? tanhf(gq) : sigm(gq);
                    sh_act[tid] = fq1(act, sc(sh_k[1 + gr]), scinv(sh_k[1 + gr]));
                }
                __syncthreads();
                float tc0 = 0.0f, oq0 = 0.0f;
                if (tid < 160) {
                    float iq = sh_act[tid], ff = sh_act[tid + 160], gg = sh_act[tid + 320];
                    oq0 = sh_act[tid + 480];
                    float cn = ff * c_m1 + iq * gg;
                    c_m0 = cn;                      // corrected c(t)
                    tc0 = tanhf(cn);
                }
                if (wid < 5) {
                    unsigned aw = warp_max_u(__float_as_uint(fabsf(tc0)));
                    if (lane == 0) atomicMax(&sh_red[10], aw);
                }
                __syncthreads();
                if (wid == 0) {
                    unsigned v = (lane == 0) ? sh_red[10] : 0u;
                    __syncwarp();
                    if (lane == 0) sh_red[10] = 0u;
                    nbar++;
                    unsigned cv = grid_bar(cb_ + 16 * CSTRIDE, v, 1, nbar * GB, lane);
                    if (lane == 0) sh_k[5] = po2k(__uint_as_float(cv));
                }
                __syncthreads();
                if (tid < 160) hp0 = oq0 * fq1(tc0, sc(sh_k[5]), scinv(sh_k[5]));
                if (wid < 5) {
                    unsigned aw = warp_max_u(__float_as_uint(fabsf(hp0)));
                    if (lane == 0) atomicMax(&sh_red[10], aw);
                }
                __syncthreads();
                if (wid == 0) {
                    unsigned v = (lane == 0) ? sh_red[10] : 0u;
                    __syncwarp();
                    if (lane == 0) sh_red[10] = 0u;
                    nbar++;
                    unsigned cv = grid_bar(cb_ + 17 * CSTRIDE, v, 1, nbar * GB, lane);
                    if (lane == 0) sh_k[6] = po2k(__uint_as_float(cv));
                }
                __syncthreads();
                if (tid < 160) {
                    float hq = fq1(hp0, sc(sh_k[6]), scinv(sh_k[6]));
                    sh_h[t & 1][b * NH + g] = hq;
                    out[((size_t)(bid * BPB + b) * T_STEPS + t) * NH + g] = hq;
                }
                __syncthreads();
            }
            // ---- full replay of step t+1 (pre1 recompute from corrected h(t)) ----
            {
                float p0 = 0.0f, p1 = 0.0f;
                const float2* px = reinterpret_cast<const float2*>(&sh_x[(t + 1) & 3][b * NI]);
                const float2* ph = reinterpret_cast<const float2*>(&sh_h[t & 1][b * NH]);
#pragma unroll
                for (int j = 0; j < NI / 2; j++) {
                    float2 v = px[j];
                    p0 = fmaf(v.x, wi[2 * j], p0); p1 = fmaf(v.y, wi[2 * j + 1], p1);
                }
#pragma unroll
                for (int j = 0; j < NH / 2; j++) {
                    float2 v = ph[j];
                    p0 = fmaf(v.x, wh[2 * j], p0); p1 = fmaf(v.y, wh[2 * j + 1], p1);
                }
                pre1 = p0 + p1;
                unsigned kp = warp_max_u(mapf(pre1));
                unsigned kn = warp_max_u(mapf(-pre1));
                if (lane == 0) { atomicMax(&sh_red[12 + gr], kp); atomicMax(&sh_red[16 + gr], kn); }
            }
            __syncthreads();
            if (wid == 0) {
                unsigned v = (lane < 8) ? sh_red[12 + lane] : 0u;
                __syncwarp();
                if (lane < 8) sh_red[12 + lane] = 0u;
                unsigned n0 = __shfl_sync(0xffffffffu, v, 4);
                unsigned n1 = __shfl_sync(0xffffffffu, v, 5);
                unsigned n2 = __shfl_sync(0xffffffffu, v, 6);
                unsigned n3 = __shfl_sync(0xffffffffu, v, 7);
                unsigned myv = v;
                if (lane == 4) myv = n2;
                if (lane == 5) myv = max(max(n0, n1), max(n2, n3));
                nbar++;
                unsigned cv = grid_bar(cb_ + 18 * CSTRIDE, myv, 6, nbar * GB, lane);
                unsigned kk = ((lane < 4) || (lane == 5)) ? cv : 0u;
#pragma unroll
                for (int o = 16; o; o >>= 1) kk = max(kk, __shfl_xor_sync(0xffffffffu, kk, o));
                int k1u = po2k(unmapf(kk));
                float s1 = sc(k1u), v1 = scinv(k1u);
                float mng = unmapf(__shfl_sync(0xffffffffu, cv, 4));
                float myp = unmapf(cv);
                float a;
                if (lane == 2) {
                    float q1 = fq1(myp, s1, v1), q2 = fq1(-mng, s1, v1);
                    a = tanhf(fmaxf(q1, -q2));
                } else {
                    a = sigm(fq1(myp, s1, v1));
                }
                int ka = po2k(fabsf(a));
                if (lane < 4) sh_k[9 + lane] = ka;
                if (lane == 0) sh_k[8] = k1u;
            }
            __syncthreads();
            {
                float gq  = fq1(pre1, sc(sh_k[8]), scinv(sh_k[8]));
                float act = (gr == 2) ? tanhf(gq) : sigm(gq);
                sh_act[tid] = fq1(act, sc(sh_k[9 + gr]), scinv(sh_k[9 + gr]));
            }
            __syncthreads();
            if (tid < 160) {
                float iq = sh_act[tid], ff = sh_act[tid + 160], gg = sh_act[tid + 320];
                oq1 = sh_act[tid + 480];
                c  = ff * c_m0 + iq * gg;
                tc1 = tanhf(c);
            }
            if (wid < 5) {
                unsigned aw = warp_max_u(__float_as_uint(fabsf(tc1)));
                if (lane == 0) atomicMax(&sh_red[10], aw);
            }
            __syncthreads();
            if (wid == 0) {
                unsigned v = (lane == 0) ? sh_red[10] : 0u;
                __syncwarp();
                if (lane == 0) sh_red[10] = 0u;
                nbar++;
                unsigned cv = grid_bar(cb_ + 24 * CSTRIDE, v, 1, nbar * GB, lane);
                if (lane == 0) sh_k[13] = po2k(__uint_as_float(cv));
            }
            __syncthreads();
            if (tid < 160) hp1 = oq1 * fq1(tc1, sc(sh_k[13]), scinv(sh_k[13]));
            if (wid < 5) {
                unsigned aw = warp_max_u(__float_as_uint(fabsf(hp1)));
                if (lane == 0) atomicMax(&sh_red[10], aw);
            }
            __syncthreads();
            if (wid == 0) {
                unsigned v = (lane == 0) ? sh_red[10] : 0u;
                __syncwarp();
                if (lane == 0) sh_red[10] = 0u;
                nbar++;
                unsigned cv = grid_bar(cb_ + 25 * CSTRIDE, v, 1, nbar * GB, lane);
                if (lane == 0) sh_k[14] = po2k(__uint_as_float(cv));
            }
            __syncthreads();
        }

        // =============== tail: final h(t+1), prediction update ===============
        if (tid < 160) {
            int kh = sh_k[14];
            float hq = fq1(hp1, sc(kh), scinv(kh));
            sh_h[(t + 1) & 1][b * NH + g] = hq;
            out[((size_t)(bid * BPB + b) * T_STEPS + (t + 1)) * NH + g] = hq;
        }
        if (tid < 7) sh_kp[tid] = sh_k[8 + tid];   // preds <- step t+1 true exponents
        __syncthreads();                                        // S6
    }
}

extern "C" void kernel_launch(void* const* d_in, const int* in_sizes, int n_in,
                              void* d_out, int out_size) {
    (void)in_sizes; (void)n_in; (void)out_size;
    qlstm_init<<<32, 512>>>();
    qlstm_main<<<GB, NT>>>((const float*)d_in[0],
                           (const float*)d_in[1],
                           (const float*)d_in[2],
                           (float*)d_out);
}

// round 17
// speedup vs baseline: 1.1603x; 1.1603x over previous
#include <cuda_runtime.h>

// ---------------------------------------------------------------------------
// Quantized LSTM, ONE grid barrier per step (R6, the proven best structure):
// full scale speculation (k1, ka[4], k3 predicted from previous step), one
// synchronous barrier reduces {per-group signed min/max of pre, max|tanh c|,
// max|h_pre|} and verifies everything; globally-uniform tiered fixups on miss.
// R16 change (only one): the barrier counter is a fire-and-forget
// red.release.add; ALL blocks poll with ld.acquire (no add-return stall).
// ---------------------------------------------------------------------------

#define GB       128
#define BPB      8
#define NT       640
#define T_STEPS  1024
#define NI       10
#define NH       20
#define NG       80
#define CSTRIDE  64              // 256B between cells
#define NCELL    16              // 0-7 main, 8 c1, 9-10 c2a, 11 c2b

__device__ __align__(128) unsigned g_ctr0[32];
__device__ unsigned g_cells[T_STEPS * NCELL * CSTRIDE];

__global__ void qlstm_init() {
    int i = blockIdx.x * blockDim.x + threadIdx.x;   // 16384 = T_STEPS*NCELL
    if (i == 0) g_ctr0[0] = 0u;
    if (i < T_STEPS * NCELL) g_cells[i * CSTRIDE] = 0u;
}

// order-preserving float<->uint key
__device__ __forceinline__ unsigned mapf(float f) {
    unsigned u = __float_as_uint(f);
    return (u & 0x80000000u) ? ~u : (u | 0x80000000u);
}
__device__ __forceinline__ float unmapf(unsigned u) {
    return __uint_as_float((u & 0x80000000u) ? (u & 0x7FFFFFFFu) : ~u);
}
// k = ceil(log2(max(m,1e-8))); scale = 2^(k-7)
__device__ __forceinline__ int po2k(float m) {
    m = fmaxf(m, 1e-8f);
    int e; float f = frexpf(m, &e);
    return (f == 0.5f) ? (e - 1) : e;
}
__device__ __forceinline__ float sc(int k)    { return __uint_as_float((unsigned)(k + 120) << 23); }
__device__ __forceinline__ float scinv(int k) { return __uint_as_float((unsigned)(134 - k) << 23); }
__device__ __forceinline__ float fq1(float x, float s, float inv) {
    float q = rintf(x * inv);
    q = fminf(fmaxf(q, -128.0f), 127.0f);
    return q * s;
}
__device__ __forceinline__ float sigm(float x) { return 1.0f / (1.0f + expf(-x)); }
__device__ __forceinline__ unsigned warp_max_u(unsigned v) {
#pragma unroll
    for (int o = 16; o; o >>= 1) v = max(v, __shfl_xor_sync(0xffffffffu, v, o));
    return v;
}
__device__ __forceinline__ void red_max_rlx(unsigned* p, unsigned v) {
    asm volatile("red.relaxed.gpu.max.u32 [%0],%1;" :: "l"(p), "r"(v) : "memory");
}
__device__ __forceinline__ void red_add_rel(unsigned* p, unsigned v) {
    asm volatile("red.release.gpu.add.u32 [%0],%1;" :: "l"(p), "r"(v) : "memory");
}
__device__ __forceinline__ unsigned ld_acq(const unsigned* p) {
    unsigned v; asm volatile("ld.acquire.gpu.u32 %0,[%1];" : "=r"(v) : "l"(p) : "memory"); return v;
}
__device__ __forceinline__ unsigned ld_rlx(const unsigned* p) {
    unsigned v; asm volatile("ld.relaxed.gpu.u32 %0,[%1];" : "=r"(v) : "l"(p) : "memory"); return v;
}

// grid round: red cells -> fire-and-forget release add -> acquire poll -> read
__device__ __forceinline__ unsigned grid_bar(unsigned* cell0, unsigned myv, int ncontrib,
                                             unsigned tgt, int lane) {
    if (lane < ncontrib) red_max_rlx(cell0 + lane * CSTRIDE, myv);
    __syncwarp();
    if (lane == 0) red_add_rel(&g_ctr0[0], 1u);          // no return-wait
    if (lane < ncontrib) { while (ld_acq(&g_ctr0[0]) < tgt) { } }
    __syncwarp();
    return (lane < ncontrib) ? ld_rlx(cell0 + lane * CSTRIDE) : 0u;
}

__global__ void __launch_bounds__(NT, 1) qlstm_main(
    const float* __restrict__ x,
    const float* __restrict__ Wih,
    const float* __restrict__ Whh,
    float* __restrict__ out)
{
    __shared__ __align__(16) float sh_h[BPB * NH];
    __shared__ __align__(16) float sh_x[BPB * NI];
    __shared__ float               sh_act[NG * BPB];
    __shared__ unsigned            sh_red[12];
    __shared__ int                 sh_k[8];   // 0:k1 1-4:ka 5:k3 6:kh 7:code/flag

    const int tid  = threadIdx.x;
    const int g    = tid / BPB;
    const int b    = tid % BPB;
    const int gr   = tid / 160;          // gate group (warp-uniform)
    const int lane = tid & 31;
    const int wid  = tid >> 5;

    if (tid < 12) sh_red[tid] = 0u;
    if (tid < 6)  sh_k[tid] = 99;        // garbage predictions -> full miss at t=0
    if (tid >= 6 && tid < 8) sh_k[tid] = 0;
    if (tid < BPB * NH) sh_h[tid] = 0.0f;
    __syncthreads();

    // ---- weight scale (block-local, once) ----
    {
        float wm = 0.0f;
        for (int k = tid; k < NG * NI; k += NT) wm = fmaxf(wm, fabsf(Wih[k]));
        for (int k = tid; k < NG * NH; k += NT) wm = fmaxf(wm, fabsf(Whh[k]));
        unsigned u = warp_max_u(__float_as_uint(wm));
        if (lane == 0) atomicMax(&sh_red[11], u);
        __syncthreads();
    }
    int kw = po2k(__uint_as_float(sh_red[11]));
    float ws = sc(kw), wsi = scinv(kw);
    __syncthreads();
    if (tid == 0) sh_red[11] = 0u;
    __syncthreads();

    float wi[NI], wh[NH];
#pragma unroll
    for (int i2 = 0; i2 < NI; i2++) wi[i2] = fq1(Wih[g * NI + i2], ws, wsi);
#pragma unroll
    for (int j2 = 0; j2 < NH; j2++) wh[j2] = fq1(Whh[g * NH + j2], ws, wsi);

    float    c = 0.0f, c_prev = 0.0f;
    unsigned nbar = 0;

    const int sq  = tid - 560;           // warps 17-19 stage x
    const int sxb = (sq >= 0) ? sq / NI : 0;
    const int sxi = (sq >= 0) ? sq % NI : 0;
    float xr = 0.0f;
    if (sq >= 0) {
        sh_x[sq] = x[((size_t)(blockIdx.x * BPB + sxb) * T_STEPS + 0) * NI + sxi];
        xr       = x[((size_t)(blockIdx.x * BPB + sxb) * T_STEPS + 1) * NI + sxi];
    }
    __syncthreads();

    for (int t = 0; t < T_STEPS; ++t) {
        const int k1p = sh_k[0];
        const int kap = sh_k[1 + gr];
        const int k3p = sh_k[5];

        // ===== speculative phase 1: pre, group min/max, activations =====
        float p0 = 0.0f, p1 = 0.0f;
        {
            const float2* px = reinterpret_cast<const float2*>(&sh_x[b * NI]);
            const float2* ph = reinterpret_cast<const float2*>(&sh_h[b * NH]);
#pragma unroll
            for (int j = 0; j < NI / 2; j++) {
                float2 v = px[j];
                p0 = fmaf(v.x, wi[2 * j], p0); p1 = fmaf(v.y, wi[2 * j + 1], p1);
            }
#pragma unroll
            for (int j = 0; j < NH / 2; j++) {
                float2 v = ph[j];
                p0 = fmaf(v.x, wh[2 * j], p0); p1 = fmaf(v.y, wh[2 * j + 1], p1);
            }
        }
        float pre = p0 + p1;

        unsigned kp = warp_max_u(mapf(pre));
        unsigned kn = warp_max_u(mapf(-pre));
        if (lane == 0) { atomicMax(&sh_red[gr], kp); atomicMax(&sh_red[4 + gr], kn); }

        {
            float gq  = fq1(pre, sc(k1p), scinv(k1p));
            float act = (gr == 2) ? tanhf(gq) : sigm(gq);
            sh_act[tid] = fq1(act, sc(kap), scinv(kap));
        }
        __syncthreads();                                        // S1
        if (sq >= 0 && t + 1 < T_STEPS) sh_x[sq] = xr;

        // ===== speculative phase 2: c update, tanh, h_pre =====
        float tc = 0.0f, oq = 0.0f, hp = 0.0f;
        if (tid < 160) {
            float iq = sh_act[tid], ff = sh_act[tid + 160], gg = sh_act[tid + 320];
            oq = sh_act[tid + 480];
            c_prev = c;
            c  = ff * c + iq * gg;
            tc = tanhf(c);
            hp = oq * fq1(tc, sc(k3p), scinv(k3p));
        }
        if (wid < 5) {
            unsigned a1 = warp_max_u(__float_as_uint(fabsf(tc)));
            unsigned a2 = warp_max_u(__float_as_uint(fabsf(hp)));
            if (lane == 0) { atomicMax(&sh_red[8], a1); atomicMax(&sh_red[9], a2); }
        }
        if (sq >= 0 && t + 2 < T_STEPS)
            xr = x[((size_t)(blockIdx.x * BPB + sxb) * T_STEPS + (t + 2)) * NI + sxi];
        __syncthreads();                                        // S2

        unsigned* cb = &g_cells[(size_t)t * NCELL * CSTRIDE];

        // ===== single grid barrier: reduce + verify everything =====
        if (wid == 0) {
            unsigned v = (lane < 10) ? sh_red[lane] : 0u;
            __syncwarp();
            if (lane < 10) sh_red[lane] = 0u;
            unsigned n0 = __shfl_sync(0xffffffffu, v, 4);
            unsigned n1 = __shfl_sync(0xffffffffu, v, 5);
            unsigned n2 = __shfl_sync(0xffffffffu, v, 6);
            unsigned n3 = __shfl_sync(0xffffffffu, v, 7);
            unsigned t8 = __shfl_sync(0xffffffffu, v, 8);
            unsigned t9 = __shfl_sync(0xffffffffu, v, 9);
            unsigned myv = v;                                   // lanes 0-3: group max(pre)
            if (lane == 4) myv = n2;                            // max(-pre) tanh group
            if (lane == 5) myv = max(max(n0, n1), max(n2, n3)); // global max(-pre)
            if (lane == 6) myv = t8;                            // max|tanh c|
            if (lane == 7) myv = t9;                            // max|h_pre spec|
            nbar++;
            unsigned cv = grid_bar(cb, myv, 8, nbar * GB, lane);

            unsigned kk = (lane < 4 || lane == 5) ? cv : 0u;    // |pre| max over octet
            kk = max(kk, __shfl_xor_sync(0xffffffffu, kk, 4));
            kk = max(kk, __shfl_xor_sync(0xffffffffu, kk, 2));
            kk = max(kk, __shfl_xor_sync(0xffffffffu, kk, 1));
            int k1 = po2k(unmapf(kk));
            float s1 = sc(k1), v1 = scinv(k1);
            float mng = unmapf(__shfl_sync(0xffffffffu, cv, 4));
            float myp = unmapf(cv);
            float a;
            if (lane == 2) {
                float q1 = fq1(myp, s1, v1), q2 = fq1(-mng, s1, v1);
                a = tanhf(fmaxf(q1, -q2));
            } else {
                a = sigm(fq1(myp, s1, v1));
            }
            int ka  = po2k(fabsf(a));
            int k3t = po2k(__uint_as_float(__shfl_sync(0xffffffffu, cv, 6)));
            int kht = po2k(__uint_as_float(__shfl_sync(0xffffffffu, cv, 7)));

            bool okl = (lane < 4) ? (ka == sh_k[1 + lane]) : true;
            unsigned bm = __ballot_sync(0xffffffffu, okl);
            int hit1 = ((bm & 0xFu) == 0xFu) && (k1 == sh_k[0]);
            int hit3 = (k3t == sh_k[5]);
            if (lane < 4) { sh_k[1 + lane] = ka; }
            if (lane == 0) {
                sh_k[0] = k1; sh_k[5] = k3t; sh_k[6] = kht;
                sh_k[7] = hit1 ? (hit3 ? 0 : 1) : 2;
                if (!hit1) sh_k[5] = k3t;      // keep true k3 regardless
            }
        }
        __syncthreads();                                        // S3

        const int code = sh_k[7];
        if (code == 0) {
            // ---- full hit: everything already computed ----
            if (tid < 160) {
                int kh = sh_k[6];
                float hq = fq1(hp, sc(kh), scinv(kh));
                sh_h[b * NH + g] = hq;
                out[((size_t)(blockIdx.x * BPB + b) * T_STEPS + t) * NH + g] = hq;
            }
        } else if (code == 1) {
            // ---- k3 miss only (c, tc valid): redo h_pre with true k3 ----
            int k3 = sh_k[5];
            if (tid < 160) hp = oq * fq1(tc, sc(k3), scinv(k3));
            if (wid < 5) {
                unsigned aw = warp_max_u(__float_as_uint(fabsf(hp)));
                if (lane == 0) atomicMax(&sh_red[10], aw);
            }
            __syncthreads();
            if (wid == 0) {
                unsigned v = (lane == 0) ? sh_red[10] : 0u;
                __syncwarp();
                if (lane == 0) sh_red[10] = 0u;
                nbar++;
                unsigned cv = grid_bar(cb + 8 * CSTRIDE, v, 1, nbar * GB, lane);
                if (lane == 0) sh_k[6] = po2k(__uint_as_float(cv));
            }
            __syncthreads();
            if (tid < 160) {
                int kh = sh_k[6];
                float hq = fq1(hp, sc(kh), scinv(kh));
                sh_h[b * NH + g] = hq;
                out[((size_t)(blockIdx.x * BPB + b) * T_STEPS + t) * NH + g] = hq;
            }
        } else {
            // ---- full miss: recompute with true k1/ka from the reduced extrema ----
            {
                int k1 = sh_k[0], kat = sh_k[1 + gr];
                float gq  = fq1(pre, sc(k1), scinv(k1));
                float act = (gr == 2) ? tanhf(gq) : sigm(gq);
                sh_act[tid] = fq1(act, sc(kat), scinv(kat));
            }
            __syncthreads();
            int k3g = sh_k[5];
            if (tid < 160) {
                float iq = sh_act[tid], ff = sh_act[tid + 160], gg = sh_act[tid + 320];
                oq = sh_act[tid + 480];
                c  = ff * c_prev + iq * gg;
                tc = tanhf(c);
                hp = oq * fq1(tc, sc(k3g), scinv(k3g));
            }
            if (wid < 5) {
                unsigned a1 = warp_max_u(__float_as_uint(fabsf(tc)));
                unsigned a2 = warp_max_u(__float_as_uint(fabsf(hp)));
                if (lane == 0) { atomicMax(&sh_red[10], a1); atomicMax(&sh_red[11], a2); }
            }
            __syncthreads();
            if (wid == 0) {
                unsigned v = (lane < 2) ? sh_red[10 + lane] : 0u;
                __syncwarp();
                if (lane < 2) sh_red[10 + lane] = 0u;
                nbar++;
                unsigned cv = grid_bar(cb + 9 * CSTRIDE, v, 2, nbar * GB, lane);
                int kx = po2k(__uint_as_float(cv));
                int k3 = __shfl_sync(0xffffffffu, kx, 0);
                int kh = __shfl_sync(0xffffffffu, kx, 1);
                if (lane == 0) {
                    sh_k[5] = k3; sh_k[6] = kh; sh_k[7] = (k3 == k3g) ? 0 : 1;
                }
            }
            __syncthreads();
            if (sh_k[7]) {   // k3 guess also missed: one more round
                int k3 = sh_k[5];
                if (tid < 160) hp = oq * fq1(tc, sc(k3), scinv(k3));
                if (wid < 5) {
                    unsigned aw = warp_max_u(__float_as_uint(fabsf(hp)));
                    if (lane == 0) atomicMax(&sh_red[10], aw);
                }
                __syncthreads();
                if (wid == 0) {
                    unsigned v = (lane == 0) ? sh_red[10] : 0u;
                    __syncwarp();
                    if (lane == 0) sh_red[10] = 0u;
                    nbar++;
                    unsigned cv = grid_bar(cb + 11 * CSTRIDE, v, 1, nbar * GB, lane);
                    if (lane == 0) sh_k[6] = po2k(__uint_as_float(cv));
                }
                __syncthreads();
            }
            if (tid < 160) {
                int kh = sh_k[6];
                float hq = fq1(hp, sc(kh), scinv(kh));
                sh_h[b * NH + g] = hq;
                out[((size_t)(blockIdx.x * BPB + b) * T_STEPS + t) * NH + g] = hq;
            }
        }
        __syncthreads();                                        // S4
    }
}

extern "C" void kernel_launch(void* const* d_in, const int* in_sizes, int n_in,
                              void* d_out, int out_size) {
    (void)in_sizes; (void)n_in; (void)out_size;
    qlstm_init<<<32, 512>>>();
    qlstm_main<<<GB, NT>>>((const float*)d_in[0],
                           (const float*)d_in[1],
                           (const float*)d_in[2],
                           (float*)d_out);
}